// round 8
// baseline (speedup 1.0000x reference)
#include <cuda_runtime.h>

// Problem constants
#define NPTS 16384
#define KNN  16
#define HDIM 64
#define CDIM 10

// Spatial grid: h=0.25 over [-5, 5]^3
#define GRID  40
#define NCELL (GRID * GRID * GRID)      // 64000
#define BMIN  (-5.0f)
#define CELLH 0.25f
#define INVH  4.0f

#define FINF  __int_as_float(0x7f800000)
#define FNINF __int_as_float(0xff800000)

// ---- scratch (__device__ globals; zero-initialized at load) ----
__device__ float4 g_pts[NPTS];
__device__ int    g_pcell[NPTS];
__device__ int    g_cnt[NCELL];      // re-zeroed by k_scan each run (invariant)
__device__ int    g_off[NCELL + 4];
__device__ int    g_cur[NCELL];
__device__ float4 g_spts[NPTS];
__device__ int    g_idx[NPTS * KNN];
__device__ float  g_A1[NPTS * HDIM];
__device__ float  g_B1[NPTS * HDIM];
__device__ float  g_A2[NPTS * HDIM];
__device__ float  g_B2[NPTS * HDIM];
__device__ int    g_gmax[HDIM];      // re-zeroed by k_out each run (invariant)

__device__ __forceinline__ int cell_of(float v) {
    int c = (int)floorf((v - BMIN) * INVH);
    return min(max(c, 0), GRID - 1);
}

// ---------------------------------------------------------------------------
// K1: pack points, assign cells, histogram
__global__ void k_prep(const float* __restrict__ pos) {
    int i = blockIdx.x * blockDim.x + threadIdx.x;
    if (i >= NPTS) return;
    float x = pos[i * 3 + 0];
    float y = pos[i * 3 + 1];
    float z = pos[i * 3 + 2];
    g_pts[i] = make_float4(x, y, z, fmaf(z, z, fmaf(y, y, x * x)));
    int c = (cell_of(z) * GRID + cell_of(y)) * GRID + cell_of(x);
    g_pcell[i] = c;
    atomicAdd(&g_cnt[c], 1);
}

// ---------------------------------------------------------------------------
// K2: single-block scan over 64000 cells (1000 thr x 64 cells each).
__global__ __launch_bounds__(1000) void k_scan() {
    __shared__ int s[1000];
    int t = threadIdx.x;
    int sum = 0;
#pragma unroll 4
    for (int k = 0; k < 16; ++k) {
        int4 c = reinterpret_cast<const int4*>(g_cnt)[t * 16 + k];
        sum += c.x + c.y + c.z + c.w;
    }
    s[t] = sum;
    __syncthreads();
    for (int off = 1; off < 1024; off <<= 1) {
        int u = (t >= off) ? s[t - off] : 0;
        __syncthreads();
        s[t] += u;
        __syncthreads();
    }
    int run = s[t] - sum;   // exclusive base
#pragma unroll 4
    for (int k = 0; k < 16; ++k) {
        int4 cc = reinterpret_cast<const int4*>(g_cnt)[t * 16 + k];
        int4 o = make_int4(run, run + cc.x, run + cc.x + cc.y,
                           run + cc.x + cc.y + cc.z);
        reinterpret_cast<int4*>(g_off)[t * 16 + k] = o;
        reinterpret_cast<int4*>(g_cur)[t * 16 + k] = o;
        reinterpret_cast<int4*>(g_cnt)[t * 16 + k] = make_int4(0, 0, 0, 0);
        run += cc.x + cc.y + cc.z + cc.w;
    }
    if (t == 999) g_off[NCELL] = NPTS;
}

// ---------------------------------------------------------------------------
// K3: scatter into cell-sorted order
__global__ void k_scatter() {
    int i = blockIdx.x * blockDim.x + threadIdx.x;
    if (i >= NPTS) return;
    int c = g_pcell[i];
    int slot = atomicAdd(&g_cur[c], 1);
    g_spts[slot] = g_pts[i];
}

// ---------------------------------------------------------------------------
// K4: exact kNN (one warp/query) + fused layer-1 projections epilogue.
// First tile: 32-lane bitonic sort -> sorted distributed top-32, tight kth.
// Later tiles: ballot filter + single-shfl-chain shift-insert per survivor.
// Row offsets fetched one-row-per-lane; empty rows skipped via ballot.
#define BITONIC32(D, J)                                                       \
    {                                                                         \
        _Pragma("unroll")                                                     \
        for (int k = 2; k <= 32; k <<= 1) {                                   \
            _Pragma("unroll")                                                 \
            for (int st = k >> 1; st > 0; st >>= 1) {                         \
                float od = __shfl_xor_sync(FULL, D, st);                      \
                int   oj = __shfl_xor_sync(FULL, J, st);                      \
                bool up = ((lane & k) == 0);                                  \
                bool lo = ((lane & st) == 0);                                 \
                bool keepMin = (lo == up);                                    \
                bool take = keepMin ? (od < D) : (od > D);                    \
                D = take ? od : D;                                            \
                J = take ? oj : J;                                            \
            }                                                                 \
        }                                                                     \
    }

#define SCANSEG(A, B)                                                         \
    for (int base = (A); base < (B); base += 32) {                            \
        int j = base + lane;                                                  \
        float d = FINF;                                                       \
        if (j < (B)) {                                                        \
            float4 cd = __ldg(&g_spts[j]);                                    \
            d = fmaf(ax, cd.x, fmaf(ay, cd.y, fmaf(az, cd.z, cd.w + pw)));    \
        }                                                                     \
        if (first) {                                                          \
            first = false;                                                    \
            BITONIC32(d, j)                                                   \
            bd = d; bj = j;                                                   \
            kth = __shfl_sync(FULL, bd, KNN - 1);                             \
        } else {                                                              \
            unsigned msk = __ballot_sync(FULL, d < kth);                      \
            if (msk) {                                                        \
                do {                                                          \
                    int src = __ffs(msk) - 1;                                 \
                    msk &= msk - 1;                                           \
                    float dw = __shfl_sync(FULL, d, src);                     \
                    int   jw = __shfl_sync(FULL, j, src);                     \
                    float pbd = __shfl_up_sync(FULL, bd, 1);                  \
                    int   pbj = __shfl_up_sync(FULL, bj, 1);                  \
                    bool ins  = dw < bd;                                      \
                    bool pins = (lane > 0) && (dw < pbd);                     \
                    bd = ins ? (pins ? pbd : dw) : bd;                        \
                    bj = ins ? (pins ? pbj : jw) : bj;                        \
                } while (msk);                                                \
                kth = __shfl_sync(FULL, bd, KNN - 1);                         \
            }                                                                 \
        }                                                                     \
    }

__global__ __launch_bounds__(128) void k_knng(const float* __restrict__ W1,
                                              const float* __restrict__ b1) {
    const unsigned FULL = 0xFFFFFFFFu;
    int warp = (blockIdx.x * 128 + threadIdx.x) >> 5;
    int lane = threadIdx.x & 31;
    float4 p = g_spts[warp];
    float pw = p.w;
    float ax = -2.0f * p.x, ay = -2.0f * p.y, az = -2.0f * p.z;
    int cx = cell_of(p.x), cy = cell_of(p.y), cz = cell_of(p.z);

    float bd = FINF;   // lane l: l-th smallest distance so far (32-deep list)
    int   bj = 0;
    float kth = FINF;  // warp-uniform (stale-safe) 16th best
    bool  first = true;

    for (int m = 1; m < GRID; ++m) {
        int zlo = max(cz - m, 0), zhi = min(cz + m, GRID - 1);
        int ylo = max(cy - m, 0), yhi = min(cy + m, GRID - 1);
        int xlo = max(cx - m, 0), xhi = min(cx + m, GRID - 1);
        int ny = yhi - ylo + 1;
        int nrows = (zhi - zlo + 1) * ny;
        // center row first at m=1 so the bitonic fill sees nearest candidates
        int rc = (m == 1) ? ((cz - zlo) * ny + (cy - ylo)) : 0;

        for (int rbase = 0; rbase < nrows; rbase += 32) {
            int rid = rbase + lane;
            int a0 = 0, a1 = 0, b0 = 0, b1r = 0;
            if (rid < nrows) {
                int z = zlo + rid / ny;
                int y = ylo + rid - (rid / ny) * ny;
                int rb = (z * GRID + y) * GRID;
                bool fullrow = (m == 1) || (abs(z - cz) == m) || (abs(y - cy) == m);
                if (fullrow) {
                    a0 = __ldg(&g_off[rb + xlo]);
                    a1 = __ldg(&g_off[rb + xhi + 1]);
                } else {
                    if (cx - m >= 0) {
                        a0 = __ldg(&g_off[rb + cx - m]);
                        a1 = __ldg(&g_off[rb + cx - m + 1]);
                    }
                    if (cx + m < GRID) {
                        b0 = __ldg(&g_off[rb + cx + m]);
                        b1r = __ldg(&g_off[rb + cx + m + 1]);
                    }
                }
            }
            int cnt = min(nrows - rbase, 32);
            unsigned nz = __ballot_sync(FULL, (rid < nrows) && ((a1 > a0) | (b1r > b0)));
            if (rbase == 0 && rc < cnt && (nz >> rc) & 1u) {
                int sa0 = __shfl_sync(FULL, a0, rc);
                int sa1 = __shfl_sync(FULL, a1, rc);
                SCANSEG(sa0, sa1)
                nz &= ~(1u << rc);
            }
            while (nz) {
                int r = __ffs(nz) - 1;
                nz &= nz - 1;
                int sa0 = __shfl_sync(FULL, a0, r);
                int sa1 = __shfl_sync(FULL, a1, r);
                SCANSEG(sa0, sa1)
                int sb0 = __shfl_sync(FULL, b0, r);
                int sb1 = __shfl_sync(FULL, b1r, r);
                SCANSEG(sb0, sb1)
            }
        }

        // exact stop: distance from p to scanned-box faces (inf at grid edge)
        float f0 = (xlo > 0)        ? (p.x - (BMIN + (float)xlo * CELLH))       : FINF;
        float f1 = (xhi < GRID - 1) ? ((BMIN + (float)(xhi + 1) * CELLH) - p.x) : FINF;
        float f2 = (ylo > 0)        ? (p.y - (BMIN + (float)ylo * CELLH))       : FINF;
        float f3 = (yhi < GRID - 1) ? ((BMIN + (float)(yhi + 1) * CELLH) - p.y) : FINF;
        float f4 = (zlo > 0)        ? (p.z - (BMIN + (float)zlo * CELLH))       : FINF;
        float f5 = (zhi < GRID - 1) ? ((BMIN + (float)(zhi + 1) * CELLH) - p.z) : FINF;
        float bb = fminf(fminf(fminf(f0, f1), fminf(f2, f3)), fminf(f4, f5));
        bb -= 1e-4f;  // fp slack on face positions
        if (kth <= bb * bb) break;
    }
    if (lane < KNN) g_idx[warp * KNN + lane] = bj;

    // Fused layer-1 projections for this query: 2 h-columns per lane.
    // A1 = x@(Wa-Wb)+b1, B1 = x@Wb ; warp-coalesced 64-float row stores.
#pragma unroll
    for (int hh = 0; hh < 2; ++hh) {
        int h = lane + hh * 32;
        float wa0 = __ldg(&W1[0 * HDIM + h]);
        float wa1 = __ldg(&W1[1 * HDIM + h]);
        float wa2 = __ldg(&W1[2 * HDIM + h]);
        float wb0 = __ldg(&W1[3 * HDIM + h]);
        float wb1 = __ldg(&W1[4 * HDIM + h]);
        float wb2 = __ldg(&W1[5 * HDIM + h]);
        float v = fmaf(p.x, wb0, fmaf(p.y, wb1, p.z * wb2));
        float u = fmaf(p.x, wa0 - wb0, fmaf(p.y, wa1 - wb1, p.z * (wa2 - wb2)))
                  + __ldg(&b1[h]);
        g_A1[warp * HDIM + h] = u;
        g_B1[warp * HDIM + h] = v;
    }
}

// ---------------------------------------------------------------------------
// K5: fused gmax1 + layer-2 projections.
// sX[i][:] = h1 = relu(A1 + max_k B1[idx]) computed on the fly, then
// A2 = h1@(W2a-W2b)+b2, B2 = h1@W2b, register-tiled 4 rows/thread.
__global__ __launch_bounds__(256) void k_feat2(const float* __restrict__ W2,
                                               const float* __restrict__ b2) {
    __shared__ float sWu[HDIM * HDIM];
    __shared__ float sWv[HDIM * HDIM];
    __shared__ float sX[64 * HDIM];
    int tid = threadIdx.x;
    for (int e = tid; e < HDIM * HDIM; e += 256) {
        int j = e >> 6, h = e & 63;
        float wb = W2[(j + HDIM) * HDIM + h];
        sWv[e] = wb;
        sWu[e] = W2[j * HDIM + h] - wb;
    }
    // gmax1 fused: build h1 tile directly in shared
    for (int e = tid; e < 64 * 16; e += 256) {
        int i = blockIdx.x * 64 + (e >> 4);
        int q = e & 15;
        const int4* row = reinterpret_cast<const int4*>(g_idx + i * KNN);
        float4 mx = make_float4(FNINF, FNINF, FNINF, FNINF);
#pragma unroll
        for (int k4 = 0; k4 < 4; ++k4) {
            int4 jj = __ldg(row + k4);
            int js[4] = {jj.x, jj.y, jj.z, jj.w};
#pragma unroll
            for (int e4 = 0; e4 < 4; ++e4) {
                float4 v = reinterpret_cast<const float4*>(g_B1)[js[e4] * 16 + q];
                mx.x = fmaxf(mx.x, v.x); mx.y = fmaxf(mx.y, v.y);
                mx.z = fmaxf(mx.z, v.z); mx.w = fmaxf(mx.w, v.w);
            }
        }
        float4 a = reinterpret_cast<const float4*>(g_A1)[i * 16 + q];
        float4 o;
        o.x = fmaxf(a.x + mx.x, 0.0f); o.y = fmaxf(a.y + mx.y, 0.0f);
        o.z = fmaxf(a.z + mx.z, 0.0f); o.w = fmaxf(a.w + mx.w, 0.0f);
        reinterpret_cast<float4*>(sX)[e] = o;
    }
    __syncthreads();

    int ty = tid >> 4, q = tid & 15;
    float4 au[4], av[4];
#pragma unroll
    for (int k = 0; k < 4; ++k) {
        au[k] = make_float4(0.f, 0.f, 0.f, 0.f);
        av[k] = make_float4(0.f, 0.f, 0.f, 0.f);
    }
#pragma unroll 4
    for (int j = 0; j < HDIM; ++j) {
        float4 wu = reinterpret_cast<const float4*>(sWu)[j * 16 + q];
        float4 wv = reinterpret_cast<const float4*>(sWv)[j * 16 + q];
#pragma unroll
        for (int k = 0; k < 4; ++k) {
            float xj = sX[(ty * 4 + k) * HDIM + j];
            au[k].x = fmaf(xj, wu.x, au[k].x); au[k].y = fmaf(xj, wu.y, au[k].y);
            au[k].z = fmaf(xj, wu.z, au[k].z); au[k].w = fmaf(xj, wu.w, au[k].w);
            av[k].x = fmaf(xj, wv.x, av[k].x); av[k].y = fmaf(xj, wv.y, av[k].y);
            av[k].z = fmaf(xj, wv.z, av[k].z); av[k].w = fmaf(xj, wv.w, av[k].w);
        }
    }
    float4 bb = reinterpret_cast<const float4*>(b2)[q];
#pragma unroll
    for (int k = 0; k < 4; ++k) {
        int i = blockIdx.x * 64 + ty * 4 + k;
        au[k].x += bb.x; au[k].y += bb.y; au[k].z += bb.z; au[k].w += bb.w;
        reinterpret_cast<float4*>(g_A2)[i * 16 + q] = au[k];
        reinterpret_cast<float4*>(g_B2)[i * 16 + q] = av[k];
    }
}

// ---------------------------------------------------------------------------
// K6: h2 = relu(A2 + max_k B2[idx]) folded into global max reduce
__global__ __launch_bounds__(256) void k_gmax2() {
    __shared__ int sg[HDIM];
    if (threadIdx.x < HDIM) sg[threadIdx.x] = 0;
    __syncthreads();
    int gt = blockIdx.x * 256 + threadIdx.x;
    int i = gt >> 4, q = gt & 15;
    const int4* row = reinterpret_cast<const int4*>(g_idx + i * KNN);
    float4 m = make_float4(FNINF, FNINF, FNINF, FNINF);
#pragma unroll
    for (int k4 = 0; k4 < 4; ++k4) {
        int4 jj = __ldg(row + k4);
        int js[4] = {jj.x, jj.y, jj.z, jj.w};
#pragma unroll
        for (int e = 0; e < 4; ++e) {
            float4 v = reinterpret_cast<const float4*>(g_B2)[js[e] * 16 + q];
            m.x = fmaxf(m.x, v.x); m.y = fmaxf(m.y, v.y);
            m.z = fmaxf(m.z, v.z); m.w = fmaxf(m.w, v.w);
        }
    }
    float4 a = reinterpret_cast<const float4*>(g_A2)[i * 16 + q];
    float4 o;
    o.x = fmaxf(a.x + m.x, 0.0f); o.y = fmaxf(a.y + m.y, 0.0f);
    o.z = fmaxf(a.z + m.z, 0.0f); o.w = fmaxf(a.w + m.w, 0.0f);
    atomicMax(&sg[q * 4 + 0], __float_as_int(o.x));
    atomicMax(&sg[q * 4 + 1], __float_as_int(o.y));
    atomicMax(&sg[q * 4 + 2], __float_as_int(o.z));
    atomicMax(&sg[q * 4 + 3], __float_as_int(o.w));
    __syncthreads();
    if (threadIdx.x < HDIM) atomicMax(&g_gmax[threadIdx.x], sg[threadIdx.x]);
}

// ---------------------------------------------------------------------------
// K7: out = g @ Wc + bc ; then re-zero g_gmax for next run
__global__ void k_out(const float* __restrict__ Wc, const float* __restrict__ bc,
                      float* __restrict__ out) {
    int c = threadIdx.x;
    if (c < CDIM) {
        float acc = bc[c];
#pragma unroll
        for (int h = 0; h < HDIM; ++h)
            acc = fmaf(__int_as_float(g_gmax[h]), Wc[h * CDIM + c], acc);
        out[c] = acc;
    }
    __syncthreads();
    if (c < HDIM) g_gmax[c] = 0;
}

// ---------------------------------------------------------------------------
extern "C" void kernel_launch(void* const* d_in, const int* in_sizes, int n_in,
                              void* d_out, int out_size) {
    const float* pos = (const float*)d_in[0];
    // d_in[1] = batch (all zeros, num_segments=1) -> unused
    const float* W1 = (const float*)d_in[2];
    const float* b1 = (const float*)d_in[3];
    const float* W2 = (const float*)d_in[4];
    const float* b2 = (const float*)d_in[5];
    const float* Wc = (const float*)d_in[6];
    const float* bc = (const float*)d_in[7];
    float* out = (float*)d_out;

    k_prep<<<NPTS / 256, 256>>>(pos);                 // 0
    k_scan<<<1, 1000>>>();                            // 1
    k_scatter<<<NPTS / 256, 256>>>();                 // 2
    k_knng<<<NPTS * 32 / 128, 128>>>(W1, b1);         // 3  <- ncu capture slot
    k_feat2<<<NPTS / 64, 256>>>(W2, b2);              // 4
    k_gmax2<<<NPTS * 16 / 256, 256>>>();              // 5
    k_out<<<1, 64>>>(Wc, bc, out);                    // 6
}

// round 9
// speedup vs baseline: 1.1979x; 1.1979x over previous
#include <cuda_runtime.h>

// Problem constants
#define NPTS 16384
#define KNN  16
#define HDIM 64
#define CDIM 10

// Spatial grid: h=0.3 over [-4.8, 4.8]^3
#define GRID  32
#define NCELL (GRID * GRID * GRID)      // 32768
#define BMIN  (-4.8f)
#define CELLH 0.3f
#define INVH  (1.0f / 0.3f)

#define FINF  __int_as_float(0x7f800000)
#define FNINF __int_as_float(0xff800000)

// ---- scratch (__device__ globals; zero-initialized at load) ----
__device__ float4 g_pts[NPTS];
__device__ int    g_pcell[NPTS];
__device__ int    g_cnt[NCELL];      // re-zeroed by k_scan each run (invariant)
__device__ int    g_off[NCELL + 4];
__device__ int    g_cur[NCELL];
__device__ float4 g_spts[NPTS];
__device__ int    g_idx[NPTS * KNN];
__device__ float  g_A1[NPTS * HDIM];
__device__ float  g_B1[NPTS * HDIM];
__device__ float  g_h1[NPTS * HDIM];
__device__ float  g_A2[NPTS * HDIM];
__device__ float  g_B2[NPTS * HDIM];
__device__ int    g_gmax[HDIM];      // re-zeroed by k_out each run (invariant)

__device__ __forceinline__ int cell_of(float v) {
    int c = (int)floorf((v - BMIN) * INVH);
    return min(max(c, 0), GRID - 1);
}

// ---------------------------------------------------------------------------
// K1: pack points, assign cells, histogram
__global__ void k_prep(const float* __restrict__ pos) {
    int i = blockIdx.x * blockDim.x + threadIdx.x;
    if (i >= NPTS) return;
    float x = pos[i * 3 + 0];
    float y = pos[i * 3 + 1];
    float z = pos[i * 3 + 2];
    g_pts[i] = make_float4(x, y, z, fmaf(z, z, fmaf(y, y, x * x)));
    int c = (cell_of(z) * GRID + cell_of(y)) * GRID + cell_of(x);
    g_pcell[i] = c;
    atomicAdd(&g_cnt[c], 1);
}

// ---------------------------------------------------------------------------
// K2: single-block scan over all 32768 cells (1024 thr x 32 cells each).
__global__ __launch_bounds__(1024) void k_scan() {
    __shared__ int s[1024];
    int t = threadIdx.x;
    int4 c[8];
    int sum = 0;
#pragma unroll
    for (int k = 0; k < 8; ++k) {
        c[k] = reinterpret_cast<const int4*>(g_cnt)[t * 8 + k];
        sum += c[k].x + c[k].y + c[k].z + c[k].w;
    }
    s[t] = sum;
    __syncthreads();
    for (int off = 1; off < 1024; off <<= 1) {
        int u = (t >= off) ? s[t - off] : 0;
        __syncthreads();
        s[t] += u;
        __syncthreads();
    }
    int run = s[t] - sum;   // exclusive base
#pragma unroll
    for (int k = 0; k < 8; ++k) {
        int4 cc = c[k];
        int4 o = make_int4(run, run + cc.x, run + cc.x + cc.y,
                           run + cc.x + cc.y + cc.z);
        reinterpret_cast<int4*>(g_off)[t * 8 + k] = o;
        reinterpret_cast<int4*>(g_cur)[t * 8 + k] = o;
        reinterpret_cast<int4*>(g_cnt)[t * 8 + k] = make_int4(0, 0, 0, 0);
        run += cc.x + cc.y + cc.z + cc.w;
    }
    if (t == 1023) g_off[NCELL] = NPTS;
}

// ---------------------------------------------------------------------------
// K3: scatter into cell-sorted order
__global__ void k_scatter() {
    int i = blockIdx.x * blockDim.x + threadIdx.x;
    if (i >= NPTS) return;
    int c = g_pcell[i];
    int slot = atomicAdd(&g_cur[c], 1);
    g_spts[slot] = g_pts[i];
}

// ---------------------------------------------------------------------------
// K4: exact kNN (one warp/query, 128-thread blocks) + fused feat1 epilogue.
// First tile: 32-lane bitonic sort -> sorted distributed top-32, tight kth.
// Later tiles: ballot filter + single-shfl-chain shift-insert per survivor.
// Row offsets fetched one-row-per-lane; empty rows skipped via ballot.
#define BITONIC32(D, J)                                                       \
    {                                                                         \
        _Pragma("unroll")                                                     \
        for (int k = 2; k <= 32; k <<= 1) {                                   \
            _Pragma("unroll")                                                 \
            for (int st = k >> 1; st > 0; st >>= 1) {                         \
                float od = __shfl_xor_sync(FULL, D, st);                      \
                int   oj = __shfl_xor_sync(FULL, J, st);                      \
                bool up = ((lane & k) == 0);                                  \
                bool lo = ((lane & st) == 0);                                 \
                bool keepMin = (lo == up);                                    \
                bool take = keepMin ? (od < D) : (od > D);                    \
                D = take ? od : D;                                            \
                J = take ? oj : J;                                            \
            }                                                                 \
        }                                                                     \
    }

#define SCANSEG(A, B)                                                         \
    for (int base = (A); base < (B); base += 32) {                            \
        int j = base + lane;                                                  \
        float d = FINF;                                                       \
        if (j < (B)) {                                                        \
            float4 cd = __ldg(&g_spts[j]);                                    \
            d = fmaf(ax, cd.x, fmaf(ay, cd.y, fmaf(az, cd.z, cd.w + pw)));    \
        }                                                                     \
        if (first) {                                                          \
            first = false;                                                    \
            BITONIC32(d, j)                                                   \
            bd = d; bj = j;                                                   \
            kth = __shfl_sync(FULL, bd, KNN - 1);                             \
        } else {                                                              \
            unsigned msk = __ballot_sync(FULL, d < kth);                      \
            if (msk) {                                                        \
                do {                                                          \
                    int src = __ffs(msk) - 1;                                 \
                    msk &= msk - 1;                                           \
                    float dw = __shfl_sync(FULL, d, src);                     \
                    int   jw = __shfl_sync(FULL, j, src);                     \
                    float pbd = __shfl_up_sync(FULL, bd, 1);                  \
                    int   pbj = __shfl_up_sync(FULL, bj, 1);                  \
                    bool ins  = dw < bd;                                      \
                    bool pins = (lane > 0) && (dw < pbd);                     \
                    bd = ins ? (pins ? pbd : dw) : bd;                        \
                    bj = ins ? (pins ? pbj : jw) : bj;                        \
                } while (msk);                                                \
                kth = __shfl_sync(FULL, bd, KNN - 1);                         \
            }                                                                 \
        }                                                                     \
    }

__global__ __launch_bounds__(128) void k_knng(const float* __restrict__ W1,
                                              const float* __restrict__ b1) {
    const unsigned FULL = 0xFFFFFFFFu;
    int warp = (blockIdx.x * 128 + threadIdx.x) >> 5;
    int lane = threadIdx.x & 31;
    float4 p = g_spts[warp];
    float pw = p.w;
    float ax = -2.0f * p.x, ay = -2.0f * p.y, az = -2.0f * p.z;
    int cx = cell_of(p.x), cy = cell_of(p.y), cz = cell_of(p.z);

    float bd = FINF;   // lane l: l-th smallest distance so far (32-deep list)
    int   bj = 0;
    float kth = FINF;  // warp-uniform (stale-safe) 16th best
    bool  first = true;

    for (int m = 1; m < GRID; ++m) {
        int zlo = max(cz - m, 0), zhi = min(cz + m, GRID - 1);
        int ylo = max(cy - m, 0), yhi = min(cy + m, GRID - 1);
        int xlo = max(cx - m, 0), xhi = min(cx + m, GRID - 1);
        int ny = yhi - ylo + 1;
        int nrows = (zhi - zlo + 1) * ny;
        // center row first at m=1 so the bitonic fill sees nearest candidates
        int rc = (m == 1) ? ((cz - zlo) * ny + (cy - ylo)) : 0;

        for (int rbase = 0; rbase < nrows; rbase += 32) {
            int rid = rbase + lane;
            int a0 = 0, a1 = 0, b0 = 0, b1r = 0;
            if (rid < nrows) {
                int z = zlo + rid / ny;
                int y = ylo + rid - (rid / ny) * ny;
                int rb = (z * GRID + y) * GRID;
                bool fullrow = (m == 1) || (abs(z - cz) == m) || (abs(y - cy) == m);
                if (fullrow) {
                    a0 = __ldg(&g_off[rb + xlo]);
                    a1 = __ldg(&g_off[rb + xhi + 1]);
                } else {
                    if (cx - m >= 0) {
                        a0 = __ldg(&g_off[rb + cx - m]);
                        a1 = __ldg(&g_off[rb + cx - m + 1]);
                    }
                    if (cx + m < GRID) {
                        b0 = __ldg(&g_off[rb + cx + m]);
                        b1r = __ldg(&g_off[rb + cx + m + 1]);
                    }
                }
            }
            int cnt = min(nrows - rbase, 32);
            unsigned nz = __ballot_sync(FULL, (rid < nrows) && ((a1 > a0) | (b1r > b0)));
            if (rbase == 0 && rc < cnt && (nz >> rc) & 1u) {
                int sa0 = __shfl_sync(FULL, a0, rc);
                int sa1 = __shfl_sync(FULL, a1, rc);
                SCANSEG(sa0, sa1)
                nz &= ~(1u << rc);
            }
            while (nz) {
                int r = __ffs(nz) - 1;
                nz &= nz - 1;
                int sa0 = __shfl_sync(FULL, a0, r);
                int sa1 = __shfl_sync(FULL, a1, r);
                SCANSEG(sa0, sa1)
                int sb0 = __shfl_sync(FULL, b0, r);
                int sb1 = __shfl_sync(FULL, b1r, r);
                SCANSEG(sb0, sb1)
            }
        }

        // exact stop: distance from p to scanned-box faces (inf at grid edge)
        float f0 = (xlo > 0)        ? (p.x - (BMIN + (float)xlo * CELLH))       : FINF;
        float f1 = (xhi < GRID - 1) ? ((BMIN + (float)(xhi + 1) * CELLH) - p.x) : FINF;
        float f2 = (ylo > 0)        ? (p.y - (BMIN + (float)ylo * CELLH))       : FINF;
        float f3 = (yhi < GRID - 1) ? ((BMIN + (float)(yhi + 1) * CELLH) - p.y) : FINF;
        float f4 = (zlo > 0)        ? (p.z - (BMIN + (float)zlo * CELLH))       : FINF;
        float f5 = (zhi < GRID - 1) ? ((BMIN + (float)(zhi + 1) * CELLH) - p.z) : FINF;
        float bb = fminf(fminf(fminf(f0, f1), fminf(f2, f3)), fminf(f4, f5));
        bb -= 1e-4f;  // fp slack on face positions
        if (kth <= bb * bb) break;
    }
    if (lane < KNN) g_idx[warp * KNN + lane] = bj;

    // Fused layer-1 projections for this query: 2 h-columns per lane.
    // A1 = x@(Wa-Wb)+b1, B1 = x@Wb ; warp-coalesced 64-float row stores.
#pragma unroll
    for (int hh = 0; hh < 2; ++hh) {
        int h = lane + hh * 32;
        float wa0 = __ldg(&W1[0 * HDIM + h]);
        float wa1 = __ldg(&W1[1 * HDIM + h]);
        float wa2 = __ldg(&W1[2 * HDIM + h]);
        float wb0 = __ldg(&W1[3 * HDIM + h]);
        float wb1 = __ldg(&W1[4 * HDIM + h]);
        float wb2 = __ldg(&W1[5 * HDIM + h]);
        float v = fmaf(p.x, wb0, fmaf(p.y, wb1, p.z * wb2));
        float u = fmaf(p.x, wa0 - wb0, fmaf(p.y, wa1 - wb1, p.z * (wa2 - wb2)))
                  + __ldg(&b1[h]);
        g_A1[warp * HDIM + h] = u;
        g_B1[warp * HDIM + h] = v;
    }
}

// ---------------------------------------------------------------------------
// K5: h1 = relu(A1 + max_k B1[idx])
__global__ __launch_bounds__(256) void k_gmax1() {
    int gt = blockIdx.x * 256 + threadIdx.x;
    int i = gt >> 4, q = gt & 15;
    const int4* row = reinterpret_cast<const int4*>(g_idx + i * KNN);
    float4 m = make_float4(FNINF, FNINF, FNINF, FNINF);
#pragma unroll
    for (int k4 = 0; k4 < 4; ++k4) {
        int4 jj = __ldg(row + k4);
        int js[4] = {jj.x, jj.y, jj.z, jj.w};
#pragma unroll
        for (int e = 0; e < 4; ++e) {
            float4 v = reinterpret_cast<const float4*>(g_B1)[js[e] * 16 + q];
            m.x = fmaxf(m.x, v.x); m.y = fmaxf(m.y, v.y);
            m.z = fmaxf(m.z, v.z); m.w = fmaxf(m.w, v.w);
        }
    }
    float4 a = reinterpret_cast<const float4*>(g_A1)[i * 16 + q];
    float4 o;
    o.x = fmaxf(a.x + m.x, 0.0f); o.y = fmaxf(a.y + m.y, 0.0f);
    o.z = fmaxf(a.z + m.z, 0.0f); o.w = fmaxf(a.w + m.w, 0.0f);
    reinterpret_cast<float4*>(g_h1)[i * 16 + q] = o;
}

// ---------------------------------------------------------------------------
// K6: layer-2 projections, register-tiled 4 rows/thread.
__global__ __launch_bounds__(256) void k_feat2(const float* __restrict__ W2,
                                               const float* __restrict__ b2) {
    __shared__ float sWu[HDIM * HDIM];
    __shared__ float sWv[HDIM * HDIM];
    __shared__ float sX[64 * HDIM];
    int tid = threadIdx.x;
    for (int e = tid; e < HDIM * HDIM; e += 256) {
        int j = e >> 6, h = e & 63;
        float wb = W2[(j + HDIM) * HDIM + h];
        sWv[e] = wb;
        sWu[e] = W2[j * HDIM + h] - wb;
    }
    for (int e = tid; e < 64 * 16; e += 256)
        reinterpret_cast<float4*>(sX)[e] =
            reinterpret_cast<const float4*>(g_h1)[blockIdx.x * 1024 + e];
    __syncthreads();

    int ty = tid >> 4, q = tid & 15;
    float4 au[4], av[4];
#pragma unroll
    for (int k = 0; k < 4; ++k) {
        au[k] = make_float4(0.f, 0.f, 0.f, 0.f);
        av[k] = make_float4(0.f, 0.f, 0.f, 0.f);
    }
#pragma unroll 4
    for (int j = 0; j < HDIM; ++j) {
        float4 wu = reinterpret_cast<const float4*>(sWu)[j * 16 + q];
        float4 wv = reinterpret_cast<const float4*>(sWv)[j * 16 + q];
#pragma unroll
        for (int k = 0; k < 4; ++k) {
            float xj = sX[(ty * 4 + k) * HDIM + j];
            au[k].x = fmaf(xj, wu.x, au[k].x); au[k].y = fmaf(xj, wu.y, au[k].y);
            au[k].z = fmaf(xj, wu.z, au[k].z); au[k].w = fmaf(xj, wu.w, au[k].w);
            av[k].x = fmaf(xj, wv.x, av[k].x); av[k].y = fmaf(xj, wv.y, av[k].y);
            av[k].z = fmaf(xj, wv.z, av[k].z); av[k].w = fmaf(xj, wv.w, av[k].w);
        }
    }
    float4 bb = reinterpret_cast<const float4*>(b2)[q];
#pragma unroll
    for (int k = 0; k < 4; ++k) {
        int i = blockIdx.x * 64 + ty * 4 + k;
        au[k].x += bb.x; au[k].y += bb.y; au[k].z += bb.z; au[k].w += bb.w;
        reinterpret_cast<float4*>(g_A2)[i * 16 + q] = au[k];
        reinterpret_cast<float4*>(g_B2)[i * 16 + q] = av[k];
    }
}

// ---------------------------------------------------------------------------
// K7: h2 = relu(A2 + max_k B2[idx]) folded into global max reduce
__global__ __launch_bounds__(256) void k_gmax2() {
    __shared__ int sg[HDIM];
    if (threadIdx.x < HDIM) sg[threadIdx.x] = 0;
    __syncthreads();
    int gt = blockIdx.x * 256 + threadIdx.x;
    int i = gt >> 4, q = gt & 15;
    const int4* row = reinterpret_cast<const int4*>(g_idx + i * KNN);
    float4 m = make_float4(FNINF, FNINF, FNINF, FNINF);
#pragma unroll
    for (int k4 = 0; k4 < 4; ++k4) {
        int4 jj = __ldg(row + k4);
        int js[4] = {jj.x, jj.y, jj.z, jj.w};
#pragma unroll
        for (int e = 0; e < 4; ++e) {
            float4 v = reinterpret_cast<const float4*>(g_B2)[js[e] * 16 + q];
            m.x = fmaxf(m.x, v.x); m.y = fmaxf(m.y, v.y);
            m.z = fmaxf(m.z, v.z); m.w = fmaxf(m.w, v.w);
        }
    }
    float4 a = reinterpret_cast<const float4*>(g_A2)[i * 16 + q];
    float4 o;
    o.x = fmaxf(a.x + m.x, 0.0f); o.y = fmaxf(a.y + m.y, 0.0f);
    o.z = fmaxf(a.z + m.z, 0.0f); o.w = fmaxf(a.w + m.w, 0.0f);
    atomicMax(&sg[q * 4 + 0], __float_as_int(o.x));
    atomicMax(&sg[q * 4 + 1], __float_as_int(o.y));
    atomicMax(&sg[q * 4 + 2], __float_as_int(o.z));
    atomicMax(&sg[q * 4 + 3], __float_as_int(o.w));
    __syncthreads();
    if (threadIdx.x < HDIM) atomicMax(&g_gmax[threadIdx.x], sg[threadIdx.x]);
}

// ---------------------------------------------------------------------------
// K8: out = g @ Wc + bc ; then re-zero g_gmax for next run
__global__ void k_out(const float* __restrict__ Wc, const float* __restrict__ bc,
                      float* __restrict__ out) {
    int c = threadIdx.x;
    if (c < CDIM) {
        float acc = bc[c];
#pragma unroll
        for (int h = 0; h < HDIM; ++h)
            acc = fmaf(__int_as_float(g_gmax[h]), Wc[h * CDIM + c], acc);
        out[c] = acc;
    }
    __syncthreads();
    if (c < HDIM) g_gmax[c] = 0;
}

// ---------------------------------------------------------------------------
extern "C" void kernel_launch(void* const* d_in, const int* in_sizes, int n_in,
                              void* d_out, int out_size) {
    const float* pos = (const float*)d_in[0];
    // d_in[1] = batch (all zeros, num_segments=1) -> unused
    const float* W1 = (const float*)d_in[2];
    const float* b1 = (const float*)d_in[3];
    const float* W2 = (const float*)d_in[4];
    const float* b2 = (const float*)d_in[5];
    const float* Wc = (const float*)d_in[6];
    const float* bc = (const float*)d_in[7];
    float* out = (float*)d_out;

    k_prep<<<NPTS / 256, 256>>>(pos);                 // 0
    k_scan<<<1, 1024>>>();                            // 1
    k_scatter<<<NPTS / 256, 256>>>();                 // 2
    k_knng<<<NPTS * 32 / 128, 128>>>(W1, b1);         // 3  <- ncu capture slot
    k_gmax1<<<NPTS * 16 / 256, 256>>>();              // 4
    k_feat2<<<NPTS / 64, 256>>>(W2, b2);              // 5
    k_gmax2<<<NPTS * 16 / 256, 256>>>();              // 6
    k_out<<<1, 64>>>(Wc, bc, out);                    // 7
}

// round 10
// speedup vs baseline: 1.3675x; 1.1416x over previous
#include <cuda_runtime.h>

// Problem constants
#define NPTS 16384
#define KNN  16
#define HDIM 64
#define CDIM 10

// Spatial grid: h=0.3 over [-4.8, 4.8]^3
#define GRID  32
#define NCELL (GRID * GRID * GRID)      // 32768
#define BMIN  (-4.8f)
#define CELLH 0.3f
#define INVH  (1.0f / 0.3f)

#define FINF  __int_as_float(0x7f800000)
#define FNINF __int_as_float(0xff800000)

// ---- scratch (__device__ globals; zero-initialized at load) ----
__device__ float4 g_pts[NPTS];
__device__ int    g_pcell[NPTS];
__device__ int    g_cnt[NCELL];      // re-zeroed by k_scan each run (invariant)
__device__ int    g_off[NCELL + 4];
__device__ int    g_cur[NCELL];
__device__ float4 g_spts[NPTS];
__device__ int    g_idx[NPTS * KNN];
__device__ float  g_A1[NPTS * HDIM];
__device__ float  g_B1[NPTS * HDIM];
__device__ float  g_h1[NPTS * HDIM];
__device__ float  g_A2[NPTS * HDIM];
__device__ float  g_B2[NPTS * HDIM];
__device__ int    g_gmax[HDIM];      // re-zeroed by k_out each run (invariant)

__device__ __forceinline__ int cell_of(float v) {
    int c = (int)floorf((v - BMIN) * INVH);
    return min(max(c, 0), GRID - 1);
}

// ---------------------------------------------------------------------------
// K1: pack points, assign cells, histogram
__global__ void k_prep(const float* __restrict__ pos) {
    int i = blockIdx.x * blockDim.x + threadIdx.x;
    if (i >= NPTS) return;
    float x = pos[i * 3 + 0];
    float y = pos[i * 3 + 1];
    float z = pos[i * 3 + 2];
    g_pts[i] = make_float4(x, y, z, fmaf(z, z, fmaf(y, y, x * x)));
    int c = (cell_of(z) * GRID + cell_of(y)) * GRID + cell_of(x);
    g_pcell[i] = c;
    atomicAdd(&g_cnt[c], 1);
}

// ---------------------------------------------------------------------------
// K2: single-block scan over all 32768 cells (1024 thr x 32 cells each).
__global__ __launch_bounds__(1024) void k_scan() {
    __shared__ int s[1024];
    int t = threadIdx.x;
    int4 c[8];
    int sum = 0;
#pragma unroll
    for (int k = 0; k < 8; ++k) {
        c[k] = reinterpret_cast<const int4*>(g_cnt)[t * 8 + k];
        sum += c[k].x + c[k].y + c[k].z + c[k].w;
    }
    s[t] = sum;
    __syncthreads();
    for (int off = 1; off < 1024; off <<= 1) {
        int u = (t >= off) ? s[t - off] : 0;
        __syncthreads();
        s[t] += u;
        __syncthreads();
    }
    int run = s[t] - sum;   // exclusive base
#pragma unroll
    for (int k = 0; k < 8; ++k) {
        int4 cc = c[k];
        int4 o = make_int4(run, run + cc.x, run + cc.x + cc.y,
                           run + cc.x + cc.y + cc.z);
        reinterpret_cast<int4*>(g_off)[t * 8 + k] = o;
        reinterpret_cast<int4*>(g_cur)[t * 8 + k] = o;
        reinterpret_cast<int4*>(g_cnt)[t * 8 + k] = make_int4(0, 0, 0, 0);
        run += cc.x + cc.y + cc.z + cc.w;
    }
    if (t == 1023) g_off[NCELL] = NPTS;
}

// ---------------------------------------------------------------------------
// K3: scatter into cell-sorted order
__global__ void k_scatter() {
    int i = blockIdx.x * blockDim.x + threadIdx.x;
    if (i >= NPTS) return;
    int c = g_pcell[i];
    int slot = atomicAdd(&g_cur[c], 1);
    g_spts[slot] = g_pts[i];
}

// ---------------------------------------------------------------------------
// K4: exact kNN (one warp/query) + fused feat1 epilogue.
// DUAL-SEGMENT tiles: two row segments per iteration, half-warp each
// (stride 16) -> ~2x lane utilization on short (~13 pt) rows.
// First tile: 32-lane bitonic sort -> sorted distributed top-32, tight kth.
// Later tiles: ballot filter + single-shfl-chain shift-insert per survivor.
#define BITONIC32(D, J)                                                       \
    {                                                                         \
        _Pragma("unroll")                                                     \
        for (int k = 2; k <= 32; k <<= 1) {                                   \
            _Pragma("unroll")                                                 \
            for (int st = k >> 1; st > 0; st >>= 1) {                         \
                float od = __shfl_xor_sync(FULL, D, st);                      \
                int   oj = __shfl_xor_sync(FULL, J, st);                      \
                bool up = ((lane & k) == 0);                                  \
                bool lo = ((lane & st) == 0);                                 \
                bool keepMin = (lo == up);                                    \
                bool take = keepMin ? (od < D) : (od > D);                    \
                D = take ? od : D;                                            \
                J = take ? oj : J;                                            \
            }                                                                 \
        }                                                                     \
    }

// scan two segments [S00,S01) and [S10,S11): lanes 0-15 on seg0, 16-31 on seg1
#define SCANPAIR(S00, S01, S10, S11)                                          \
    {                                                                         \
        int mlo = (lane < 16) ? (S00) : (S10);                                \
        int mhi = (lane < 16) ? (S01) : (S11);                                \
        int sub = lane & 15;                                                  \
        for (int base = 0;; base += 16) {                                     \
            int j = mlo + base + sub;                                         \
            float d = FINF;                                                   \
            if (j < mhi) {                                                    \
                float4 cd = __ldg(&g_spts[j]);                                \
                d = fmaf(ax, cd.x, fmaf(ay, cd.y, fmaf(az, cd.z, cd.w + pw)));\
            }                                                                 \
            if (first) {                                                      \
                first = false;                                                \
                BITONIC32(d, j)                                               \
                bd = d; bj = j;                                               \
                kth = __shfl_sync(FULL, bd, KNN - 1);                         \
            } else {                                                          \
                unsigned msk = __ballot_sync(FULL, d < kth);                  \
                if (msk) {                                                    \
                    do {                                                      \
                        int src = __ffs(msk) - 1;                             \
                        msk &= msk - 1;                                       \
                        float dw = __shfl_sync(FULL, d, src);                 \
                        int   jw = __shfl_sync(FULL, j, src);                 \
                        float pbd = __shfl_up_sync(FULL, bd, 1);              \
                        int   pbj = __shfl_up_sync(FULL, bj, 1);              \
                        bool ins  = dw < bd;                                  \
                        bool pins = (lane > 0) && (dw < pbd);                 \
                        bd = ins ? (pins ? pbd : dw) : bd;                    \
                        bj = ins ? (pins ? pbj : jw) : bj;                    \
                    } while (msk);                                            \
                    kth = __shfl_sync(FULL, bd, KNN - 1);                     \
                }                                                             \
            }                                                                 \
            unsigned more = __ballot_sync(FULL, mlo + base + 16 < mhi);       \
            if (!more) break;                                                 \
        }                                                                     \
    }

__global__ __launch_bounds__(128) void k_knng(const float* __restrict__ W1,
                                              const float* __restrict__ b1) {
    const unsigned FULL = 0xFFFFFFFFu;
    int warp = (blockIdx.x * 128 + threadIdx.x) >> 5;
    int lane = threadIdx.x & 31;
    float4 p = g_spts[warp];
    float pw = p.w;
    float ax = -2.0f * p.x, ay = -2.0f * p.y, az = -2.0f * p.z;
    int cx = cell_of(p.x), cy = cell_of(p.y), cz = cell_of(p.z);

    float bd = FINF;   // lane l: l-th smallest distance so far (32-deep list)
    int   bj = 0;
    float kth = FINF;  // warp-uniform (stale-safe) 16th best
    bool  first = true;

    for (int m = 1; m < GRID; ++m) {
        int zlo = max(cz - m, 0), zhi = min(cz + m, GRID - 1);
        int ylo = max(cy - m, 0), yhi = min(cy + m, GRID - 1);
        int xlo = max(cx - m, 0), xhi = min(cx + m, GRID - 1);
        int ny = yhi - ylo + 1;
        int nrows = (zhi - zlo + 1) * ny;
        // center row first at m=1 so the bitonic fill sees nearest candidates
        int rc = (m == 1) ? ((cz - zlo) * ny + (cy - ylo)) : 0;

        for (int rbase = 0; rbase < nrows; rbase += 32) {
            int rid = rbase + lane;
            int a0 = 0, a1 = 0, b0 = 0, b1r = 0;
            if (rid < nrows) {
                int z = zlo + rid / ny;
                int y = ylo + rid - (rid / ny) * ny;
                int rb = (z * GRID + y) * GRID;
                bool fullrow = (m == 1) || (abs(z - cz) == m) || (abs(y - cy) == m);
                if (fullrow) {
                    a0 = __ldg(&g_off[rb + xlo]);
                    a1 = __ldg(&g_off[rb + xhi + 1]);
                } else {
                    if (cx - m >= 0) {
                        a0 = __ldg(&g_off[rb + cx - m]);
                        a1 = __ldg(&g_off[rb + cx - m + 1]);
                    }
                    if (cx + m < GRID) {
                        b0 = __ldg(&g_off[rb + cx + m]);
                        b1r = __ldg(&g_off[rb + cx + m + 1]);
                    }
                }
            }
            unsigned nA = __ballot_sync(FULL, (rid < nrows) && (a1 > a0));
            unsigned nB = __ballot_sync(FULL, (rid < nrows) && (b1r > b0));
            bool fp = (m == 1) && (rbase == 0) && ((nA >> rc) & 1u);
            while (nA | nB) {
                int r0, r1 = -1;
                bool f0 = false, f1 = false;
                if (fp) { r0 = rc; nA &= ~(1u << rc); fp = false; }
                else if (nA) { r0 = __ffs(nA) - 1; nA &= nA - 1; }
                else { r0 = __ffs(nB) - 1; f0 = true; nB &= nB - 1; }
                if (nA) { r1 = __ffs(nA) - 1; nA &= nA - 1; }
                else if (nB) { r1 = __ffs(nB) - 1; f1 = true; nB &= nB - 1; }
                int s00 = __shfl_sync(FULL, f0 ? b0 : a0, r0);
                int s01 = __shfl_sync(FULL, f0 ? b1r : a1, r0);
                int s10 = 0, s11 = 0;
                if (r1 >= 0) {
                    s10 = __shfl_sync(FULL, f1 ? b0 : a0, r1);
                    s11 = __shfl_sync(FULL, f1 ? b1r : a1, r1);
                }
                SCANPAIR(s00, s01, s10, s11)
            }
        }

        // exact stop: distance from p to scanned-box faces (inf at grid edge)
        float f0 = (xlo > 0)        ? (p.x - (BMIN + (float)xlo * CELLH))       : FINF;
        float f1 = (xhi < GRID - 1) ? ((BMIN + (float)(xhi + 1) * CELLH) - p.x) : FINF;
        float f2 = (ylo > 0)        ? (p.y - (BMIN + (float)ylo * CELLH))       : FINF;
        float f3 = (yhi < GRID - 1) ? ((BMIN + (float)(yhi + 1) * CELLH) - p.y) : FINF;
        float f4 = (zlo > 0)        ? (p.z - (BMIN + (float)zlo * CELLH))       : FINF;
        float f5 = (zhi < GRID - 1) ? ((BMIN + (float)(zhi + 1) * CELLH) - p.z) : FINF;
        float bb = fminf(fminf(fminf(f0, f1), fminf(f2, f3)), fminf(f4, f5));
        bb -= 1e-4f;  // fp slack on face positions
        if (kth <= bb * bb) break;
    }
    if (lane < KNN) g_idx[warp * KNN + lane] = bj;

    // Fused layer-1 projections for this query: 2 h-columns per lane.
#pragma unroll
    for (int hh = 0; hh < 2; ++hh) {
        int h = lane + hh * 32;
        float wa0 = __ldg(&W1[0 * HDIM + h]);
        float wa1 = __ldg(&W1[1 * HDIM + h]);
        float wa2 = __ldg(&W1[2 * HDIM + h]);
        float wb0 = __ldg(&W1[3 * HDIM + h]);
        float wb1 = __ldg(&W1[4 * HDIM + h]);
        float wb2 = __ldg(&W1[5 * HDIM + h]);
        float v = fmaf(p.x, wb0, fmaf(p.y, wb1, p.z * wb2));
        float u = fmaf(p.x, wa0 - wb0, fmaf(p.y, wa1 - wb1, p.z * (wa2 - wb2)))
                  + __ldg(&b1[h]);
        g_A1[warp * HDIM + h] = u;
        g_B1[warp * HDIM + h] = v;
    }
}

// ---------------------------------------------------------------------------
// K5: h1 = relu(A1 + max_k B1[idx])
__global__ __launch_bounds__(256) void k_gmax1() {
    int gt = blockIdx.x * 256 + threadIdx.x;
    int i = gt >> 4, q = gt & 15;
    const int4* row = reinterpret_cast<const int4*>(g_idx + i * KNN);
    float4 m = make_float4(FNINF, FNINF, FNINF, FNINF);
#pragma unroll
    for (int k4 = 0; k4 < 4; ++k4) {
        int4 jj = __ldg(row + k4);
        int js[4] = {jj.x, jj.y, jj.z, jj.w};
#pragma unroll
        for (int e = 0; e < 4; ++e) {
            float4 v = reinterpret_cast<const float4*>(g_B1)[js[e] * 16 + q];
            m.x = fmaxf(m.x, v.x); m.y = fmaxf(m.y, v.y);
            m.z = fmaxf(m.z, v.z); m.w = fmaxf(m.w, v.w);
        }
    }
    float4 a = reinterpret_cast<const float4*>(g_A1)[i * 16 + q];
    float4 o;
    o.x = fmaxf(a.x + m.x, 0.0f); o.y = fmaxf(a.y + m.y, 0.0f);
    o.z = fmaxf(a.z + m.z, 0.0f); o.w = fmaxf(a.w + m.w, 0.0f);
    reinterpret_cast<float4*>(g_h1)[i * 16 + q] = o;
}

// ---------------------------------------------------------------------------
// K6: layer-2 projections, register-tiled 4 rows/thread.
__global__ __launch_bounds__(256) void k_feat2(const float* __restrict__ W2,
                                               const float* __restrict__ b2) {
    __shared__ float sWu[HDIM * HDIM];
    __shared__ float sWv[HDIM * HDIM];
    __shared__ float sX[64 * HDIM];
    int tid = threadIdx.x;
    for (int e = tid; e < HDIM * HDIM; e += 256) {
        int j = e >> 6, h = e & 63;
        float wb = W2[(j + HDIM) * HDIM + h];
        sWv[e] = wb;
        sWu[e] = W2[j * HDIM + h] - wb;
    }
    for (int e = tid; e < 64 * 16; e += 256)
        reinterpret_cast<float4*>(sX)[e] =
            reinterpret_cast<const float4*>(g_h1)[blockIdx.x * 1024 + e];
    __syncthreads();

    int ty = tid >> 4, q = tid & 15;
    float4 au[4], av[4];
#pragma unroll
    for (int k = 0; k < 4; ++k) {
        au[k] = make_float4(0.f, 0.f, 0.f, 0.f);
        av[k] = make_float4(0.f, 0.f, 0.f, 0.f);
    }
#pragma unroll 4
    for (int j = 0; j < HDIM; ++j) {
        float4 wu = reinterpret_cast<const float4*>(sWu)[j * 16 + q];
        float4 wv = reinterpret_cast<const float4*>(sWv)[j * 16 + q];
#pragma unroll
        for (int k = 0; k < 4; ++k) {
            float xj = sX[(ty * 4 + k) * HDIM + j];
            au[k].x = fmaf(xj, wu.x, au[k].x); au[k].y = fmaf(xj, wu.y, au[k].y);
            au[k].z = fmaf(xj, wu.z, au[k].z); au[k].w = fmaf(xj, wu.w, au[k].w);
            av[k].x = fmaf(xj, wv.x, av[k].x); av[k].y = fmaf(xj, wv.y, av[k].y);
            av[k].z = fmaf(xj, wv.z, av[k].z); av[k].w = fmaf(xj, wv.w, av[k].w);
        }
    }
    float4 bb = reinterpret_cast<const float4*>(b2)[q];
#pragma unroll
    for (int k = 0; k < 4; ++k) {
        int i = blockIdx.x * 64 + ty * 4 + k;
        au[k].x += bb.x; au[k].y += bb.y; au[k].z += bb.z; au[k].w += bb.w;
        reinterpret_cast<float4*>(g_A2)[i * 16 + q] = au[k];
        reinterpret_cast<float4*>(g_B2)[i * 16 + q] = av[k];
    }
}

// ---------------------------------------------------------------------------
// K7: h2 = relu(A2 + max_k B2[idx]) folded into global max reduce
__global__ __launch_bounds__(256) void k_gmax2() {
    __shared__ int sg[HDIM];
    if (threadIdx.x < HDIM) sg[threadIdx.x] = 0;
    __syncthreads();
    int gt = blockIdx.x * 256 + threadIdx.x;
    int i = gt >> 4, q = gt & 15;
    const int4* row = reinterpret_cast<const int4*>(g_idx + i * KNN);
    float4 m = make_float4(FNINF, FNINF, FNINF, FNINF);
#pragma unroll
    for (int k4 = 0; k4 < 4; ++k4) {
        int4 jj = __ldg(row + k4);
        int js[4] = {jj.x, jj.y, jj.z, jj.w};
#pragma unroll
        for (int e = 0; e < 4; ++e) {
            float4 v = reinterpret_cast<const float4*>(g_B2)[js[e] * 16 + q];
            m.x = fmaxf(m.x, v.x); m.y = fmaxf(m.y, v.y);
            m.z = fmaxf(m.z, v.z); m.w = fmaxf(m.w, v.w);
        }
    }
    float4 a = reinterpret_cast<const float4*>(g_A2)[i * 16 + q];
    float4 o;
    o.x = fmaxf(a.x + m.x, 0.0f); o.y = fmaxf(a.y + m.y, 0.0f);
    o.z = fmaxf(a.z + m.z, 0.0f); o.w = fmaxf(a.w + m.w, 0.0f);
    atomicMax(&sg[q * 4 + 0], __float_as_int(o.x));
    atomicMax(&sg[q * 4 + 1], __float_as_int(o.y));
    atomicMax(&sg[q * 4 + 2], __float_as_int(o.z));
    atomicMax(&sg[q * 4 + 3], __float_as_int(o.w));
    __syncthreads();
    if (threadIdx.x < HDIM) atomicMax(&g_gmax[threadIdx.x], sg[threadIdx.x]);
}

// ---------------------------------------------------------------------------
// K8: out = g @ Wc + bc ; then re-zero g_gmax for next run
__global__ void k_out(const float* __restrict__ Wc, const float* __restrict__ bc,
                      float* __restrict__ out) {
    int c = threadIdx.x;
    if (c < CDIM) {
        float acc = bc[c];
#pragma unroll
        for (int h = 0; h < HDIM; ++h)
            acc = fmaf(__int_as_float(g_gmax[h]), Wc[h * CDIM + c], acc);
        out[c] = acc;
    }
    __syncthreads();
    if (c < HDIM) g_gmax[c] = 0;
}

// ---------------------------------------------------------------------------
extern "C" void kernel_launch(void* const* d_in, const int* in_sizes, int n_in,
                              void* d_out, int out_size) {
    const float* pos = (const float*)d_in[0];
    // d_in[1] = batch (all zeros, num_segments=1) -> unused
    const float* W1 = (const float*)d_in[2];
    const float* b1 = (const float*)d_in[3];
    const float* W2 = (const float*)d_in[4];
    const float* b2 = (const float*)d_in[5];
    const float* Wc = (const float*)d_in[6];
    const float* bc = (const float*)d_in[7];
    float* out = (float*)d_out;

    k_prep<<<NPTS / 256, 256>>>(pos);                 // 0
    k_scan<<<1, 1024>>>();                            // 1
    k_scatter<<<NPTS / 256, 256>>>();                 // 2
    k_knng<<<NPTS * 32 / 128, 128>>>(W1, b1);         // 3  <- ncu capture slot
    k_gmax1<<<NPTS * 16 / 256, 256>>>();              // 4
    k_feat2<<<NPTS / 64, 256>>>(W2, b2);              // 5
    k_gmax2<<<NPTS * 16 / 256, 256>>>();              // 6
    k_out<<<1, 64>>>(Wc, bc, out);                    // 7
}

// round 11
// speedup vs baseline: 1.4263x; 1.0430x over previous
#include <cuda_runtime.h>

// Problem constants
#define NPTS 16384
#define KNN  16
#define HDIM 64
#define CDIM 10

// Spatial grid: h=0.3 over [-4.8, 4.8]^3
#define GRID  32
#define NCELL (GRID * GRID * GRID)      // 32768
#define BMIN  (-4.8f)
#define CELLH 0.3f
#define INVH  (1.0f / 0.3f)

#define FINF  __int_as_float(0x7f800000)
#define FNINF __int_as_float(0xff800000)

// ---- scratch (__device__ globals; zero-initialized at load) ----
__device__ float4 g_pts[NPTS];
__device__ int    g_pcell[NPTS];
__device__ int    g_cnt[NCELL];      // re-zeroed by k_scan each run (invariant)
__device__ int    g_off[NCELL + 4];
__device__ int    g_cur[NCELL];
__device__ float4 g_spts[NPTS];
__device__ int    g_idx[NPTS * KNN];
__device__ float  g_A1[NPTS * HDIM];
__device__ float  g_B1[NPTS * HDIM];
__device__ float  g_A2[NPTS * HDIM];
__device__ float  g_B2[NPTS * HDIM];
__device__ int    g_gmax[HDIM];      // re-zeroed by last gmax2 block (invariant)
__device__ int    g_tick;            // ticket; re-zeroed by last gmax2 block

__device__ __forceinline__ int cell_of(float v) {
    int c = (int)floorf((v - BMIN) * INVH);
    return min(max(c, 0), GRID - 1);
}

// ---------------------------------------------------------------------------
// K1: pack points, assign cells, histogram
__global__ void k_prep(const float* __restrict__ pos) {
    int i = blockIdx.x * blockDim.x + threadIdx.x;
    if (i >= NPTS) return;
    float x = pos[i * 3 + 0];
    float y = pos[i * 3 + 1];
    float z = pos[i * 3 + 2];
    g_pts[i] = make_float4(x, y, z, fmaf(z, z, fmaf(y, y, x * x)));
    int c = (cell_of(z) * GRID + cell_of(y)) * GRID + cell_of(x);
    g_pcell[i] = c;
    atomicAdd(&g_cnt[c], 1);
}

// ---------------------------------------------------------------------------
// K2: single-block scan over all 32768 cells (1024 thr x 32 cells each).
__global__ __launch_bounds__(1024) void k_scan() {
    __shared__ int s[1024];
    int t = threadIdx.x;
    int4 c[8];
    int sum = 0;
#pragma unroll
    for (int k = 0; k < 8; ++k) {
        c[k] = reinterpret_cast<const int4*>(g_cnt)[t * 8 + k];
        sum += c[k].x + c[k].y + c[k].z + c[k].w;
    }
    s[t] = sum;
    __syncthreads();
    for (int off = 1; off < 1024; off <<= 1) {
        int u = (t >= off) ? s[t - off] : 0;
        __syncthreads();
        s[t] += u;
        __syncthreads();
    }
    int run = s[t] - sum;   // exclusive base
#pragma unroll
    for (int k = 0; k < 8; ++k) {
        int4 cc = c[k];
        int4 o = make_int4(run, run + cc.x, run + cc.x + cc.y,
                           run + cc.x + cc.y + cc.z);
        reinterpret_cast<int4*>(g_off)[t * 8 + k] = o;
        reinterpret_cast<int4*>(g_cur)[t * 8 + k] = o;
        reinterpret_cast<int4*>(g_cnt)[t * 8 + k] = make_int4(0, 0, 0, 0);
        run += cc.x + cc.y + cc.z + cc.w;
    }
    if (t == 1023) g_off[NCELL] = NPTS;
}

// ---------------------------------------------------------------------------
// K3: scatter into cell-sorted order
__global__ void k_scatter() {
    int i = blockIdx.x * blockDim.x + threadIdx.x;
    if (i >= NPTS) return;
    int c = g_pcell[i];
    int slot = atomicAdd(&g_cur[c], 1);
    g_spts[slot] = g_pts[i];
}

// ---------------------------------------------------------------------------
// K4: exact kNN (one warp/query) + fused feat1 epilogue.
// DUAL-SEGMENT tiles: two row segments per iteration, half-warp each.
#define BITONIC32(D, J)                                                       \
    {                                                                         \
        _Pragma("unroll")                                                     \
        for (int k = 2; k <= 32; k <<= 1) {                                   \
            _Pragma("unroll")                                                 \
            for (int st = k >> 1; st > 0; st >>= 1) {                         \
                float od = __shfl_xor_sync(FULL, D, st);                      \
                int   oj = __shfl_xor_sync(FULL, J, st);                      \
                bool up = ((lane & k) == 0);                                  \
                bool lo = ((lane & st) == 0);                                 \
                bool keepMin = (lo == up);                                    \
                bool take = keepMin ? (od < D) : (od > D);                    \
                D = take ? od : D;                                            \
                J = take ? oj : J;                                            \
            }                                                                 \
        }                                                                     \
    }

#define SCANPAIR(S00, S01, S10, S11)                                          \
    {                                                                         \
        int mlo = (lane < 16) ? (S00) : (S10);                                \
        int mhi = (lane < 16) ? (S01) : (S11);                                \
        int sub = lane & 15;                                                  \
        for (int base = 0;; base += 16) {                                     \
            int j = mlo + base + sub;                                         \
            float d = FINF;                                                   \
            if (j < mhi) {                                                    \
                float4 cd = __ldg(&g_spts[j]);                                \
                d = fmaf(ax, cd.x, fmaf(ay, cd.y, fmaf(az, cd.z, cd.w + pw)));\
            }                                                                 \
            if (first) {                                                      \
                first = false;                                                \
                BITONIC32(d, j)                                               \
                bd = d; bj = j;                                               \
                kth = __shfl_sync(FULL, bd, KNN - 1);                         \
            } else {                                                          \
                unsigned msk = __ballot_sync(FULL, d < kth);                  \
                if (msk) {                                                    \
                    do {                                                      \
                        int src = __ffs(msk) - 1;                             \
                        msk &= msk - 1;                                       \
                        float dw = __shfl_sync(FULL, d, src);                 \
                        int   jw = __shfl_sync(FULL, j, src);                 \
                        float pbd = __shfl_up_sync(FULL, bd, 1);              \
                        int   pbj = __shfl_up_sync(FULL, bj, 1);              \
                        bool ins  = dw < bd;                                  \
                        bool pins = (lane > 0) && (dw < pbd);                 \
                        bd = ins ? (pins ? pbd : dw) : bd;                    \
                        bj = ins ? (pins ? pbj : jw) : bj;                    \
                    } while (msk);                                            \
                    kth = __shfl_sync(FULL, bd, KNN - 1);                     \
                }                                                             \
            }                                                                 \
            unsigned more = __ballot_sync(FULL, mlo + base + 16 < mhi);       \
            if (!more) break;                                                 \
        }                                                                     \
    }

__global__ __launch_bounds__(128) void k_knng(const float* __restrict__ W1,
                                              const float* __restrict__ b1) {
    const unsigned FULL = 0xFFFFFFFFu;
    int warp = (blockIdx.x * 128 + threadIdx.x) >> 5;
    int lane = threadIdx.x & 31;
    float4 p = g_spts[warp];
    float pw = p.w;
    float ax = -2.0f * p.x, ay = -2.0f * p.y, az = -2.0f * p.z;
    int cx = cell_of(p.x), cy = cell_of(p.y), cz = cell_of(p.z);

    float bd = FINF;   // lane l: l-th smallest distance so far (32-deep list)
    int   bj = 0;
    float kth = FINF;  // warp-uniform (stale-safe) 16th best
    bool  first = true;

    for (int m = 1; m < GRID; ++m) {
        int zlo = max(cz - m, 0), zhi = min(cz + m, GRID - 1);
        int ylo = max(cy - m, 0), yhi = min(cy + m, GRID - 1);
        int xlo = max(cx - m, 0), xhi = min(cx + m, GRID - 1);
        int ny = yhi - ylo + 1;
        int nrows = (zhi - zlo + 1) * ny;
        int rc = (m == 1) ? ((cz - zlo) * ny + (cy - ylo)) : 0;

        for (int rbase = 0; rbase < nrows; rbase += 32) {
            int rid = rbase + lane;
            int a0 = 0, a1 = 0, b0 = 0, b1r = 0;
            if (rid < nrows) {
                int z = zlo + rid / ny;
                int y = ylo + rid - (rid / ny) * ny;
                int rb = (z * GRID + y) * GRID;
                bool fullrow = (m == 1) || (abs(z - cz) == m) || (abs(y - cy) == m);
                if (fullrow) {
                    a0 = __ldg(&g_off[rb + xlo]);
                    a1 = __ldg(&g_off[rb + xhi + 1]);
                } else {
                    if (cx - m >= 0) {
                        a0 = __ldg(&g_off[rb + cx - m]);
                        a1 = __ldg(&g_off[rb + cx - m + 1]);
                    }
                    if (cx + m < GRID) {
                        b0 = __ldg(&g_off[rb + cx + m]);
                        b1r = __ldg(&g_off[rb + cx + m + 1]);
                    }
                }
            }
            unsigned nA = __ballot_sync(FULL, (rid < nrows) && (a1 > a0));
            unsigned nB = __ballot_sync(FULL, (rid < nrows) && (b1r > b0));
            bool fp = (m == 1) && (rbase == 0) && ((nA >> rc) & 1u);
            while (nA | nB) {
                int r0, r1 = -1;
                bool f0 = false, f1 = false;
                if (fp) { r0 = rc; nA &= ~(1u << rc); fp = false; }
                else if (nA) { r0 = __ffs(nA) - 1; nA &= nA - 1; }
                else { r0 = __ffs(nB) - 1; f0 = true; nB &= nB - 1; }
                if (nA) { r1 = __ffs(nA) - 1; nA &= nA - 1; }
                else if (nB) { r1 = __ffs(nB) - 1; f1 = true; nB &= nB - 1; }
                int s00 = __shfl_sync(FULL, f0 ? b0 : a0, r0);
                int s01 = __shfl_sync(FULL, f0 ? b1r : a1, r0);
                int s10 = 0, s11 = 0;
                if (r1 >= 0) {
                    s10 = __shfl_sync(FULL, f1 ? b0 : a0, r1);
                    s11 = __shfl_sync(FULL, f1 ? b1r : a1, r1);
                }
                SCANPAIR(s00, s01, s10, s11)
            }
        }

        float f0 = (xlo > 0)        ? (p.x - (BMIN + (float)xlo * CELLH))       : FINF;
        float f1 = (xhi < GRID - 1) ? ((BMIN + (float)(xhi + 1) * CELLH) - p.x) : FINF;
        float f2 = (ylo > 0)        ? (p.y - (BMIN + (float)ylo * CELLH))       : FINF;
        float f3 = (yhi < GRID - 1) ? ((BMIN + (float)(yhi + 1) * CELLH) - p.y) : FINF;
        float f4 = (zlo > 0)        ? (p.z - (BMIN + (float)zlo * CELLH))       : FINF;
        float f5 = (zhi < GRID - 1) ? ((BMIN + (float)(zhi + 1) * CELLH) - p.z) : FINF;
        float bb = fminf(fminf(fminf(f0, f1), fminf(f2, f3)), fminf(f4, f5));
        bb -= 1e-4f;  // fp slack on face positions
        if (kth <= bb * bb) break;
    }
    if (lane < KNN) g_idx[warp * KNN + lane] = bj;

    // Fused layer-1 projections for this query: 2 h-columns per lane.
#pragma unroll
    for (int hh = 0; hh < 2; ++hh) {
        int h = lane + hh * 32;
        float wa0 = __ldg(&W1[0 * HDIM + h]);
        float wa1 = __ldg(&W1[1 * HDIM + h]);
        float wa2 = __ldg(&W1[2 * HDIM + h]);
        float wb0 = __ldg(&W1[3 * HDIM + h]);
        float wb1 = __ldg(&W1[4 * HDIM + h]);
        float wb2 = __ldg(&W1[5 * HDIM + h]);
        float v = fmaf(p.x, wb0, fmaf(p.y, wb1, p.z * wb2));
        float u = fmaf(p.x, wa0 - wb0, fmaf(p.y, wa1 - wb1, p.z * (wa2 - wb2)))
                  + __ldg(&b1[h]);
        g_A1[warp * HDIM + h] = u;
        g_B1[warp * HDIM + h] = v;
    }
}

// ---------------------------------------------------------------------------
// K5: fused gmax1 + layer-2 projections.
// Phase A: h1 tile = relu(A1 + max_k B1[idx]) built directly in shared.
// Phase B: A2 = h1@(W2a-W2b)+b2, B2 = h1@W2b, register-tiled 4 rows/thread.
__global__ __launch_bounds__(256) void k_feat2(const float* __restrict__ W2,
                                               const float* __restrict__ b2) {
    __shared__ float sWu[HDIM * HDIM];
    __shared__ float sWv[HDIM * HDIM];
    __shared__ float sX[64 * HDIM];
    int tid = threadIdx.x;
    // Phase A: gather-max into sX (issues long-latency random gathers early)
    for (int e = tid; e < 64 * 16; e += 256) {
        int i = blockIdx.x * 64 + (e >> 4);
        int q = e & 15;
        const int4* row = reinterpret_cast<const int4*>(g_idx + i * KNN);
        float4 mx = make_float4(FNINF, FNINF, FNINF, FNINF);
#pragma unroll
        for (int k4 = 0; k4 < 4; ++k4) {
            int4 jj = __ldg(row + k4);
            int js[4] = {jj.x, jj.y, jj.z, jj.w};
#pragma unroll
            for (int e4 = 0; e4 < 4; ++e4) {
                float4 v = reinterpret_cast<const float4*>(g_B1)[js[e4] * 16 + q];
                mx.x = fmaxf(mx.x, v.x); mx.y = fmaxf(mx.y, v.y);
                mx.z = fmaxf(mx.z, v.z); mx.w = fmaxf(mx.w, v.w);
            }
        }
        float4 a = reinterpret_cast<const float4*>(g_A1)[i * 16 + q];
        float4 o;
        o.x = fmaxf(a.x + mx.x, 0.0f); o.y = fmaxf(a.y + mx.y, 0.0f);
        o.z = fmaxf(a.z + mx.z, 0.0f); o.w = fmaxf(a.w + mx.w, 0.0f);
        reinterpret_cast<float4*>(sX)[e] = o;
    }
    // weight staging (independent of phase A loads; overlaps)
    for (int e = tid; e < HDIM * HDIM; e += 256) {
        int j = e >> 6, h = e & 63;
        float wb = W2[(j + HDIM) * HDIM + h];
        sWv[e] = wb;
        sWu[e] = W2[j * HDIM + h] - wb;
    }
    __syncthreads();

    int ty = tid >> 4, q = tid & 15;
    float4 au[4], av[4];
#pragma unroll
    for (int k = 0; k < 4; ++k) {
        au[k] = make_float4(0.f, 0.f, 0.f, 0.f);
        av[k] = make_float4(0.f, 0.f, 0.f, 0.f);
    }
#pragma unroll 4
    for (int j = 0; j < HDIM; ++j) {
        float4 wu = reinterpret_cast<const float4*>(sWu)[j * 16 + q];
        float4 wv = reinterpret_cast<const float4*>(sWv)[j * 16 + q];
#pragma unroll
        for (int k = 0; k < 4; ++k) {
            float xj = sX[(ty * 4 + k) * HDIM + j];
            au[k].x = fmaf(xj, wu.x, au[k].x); au[k].y = fmaf(xj, wu.y, au[k].y);
            au[k].z = fmaf(xj, wu.z, au[k].z); au[k].w = fmaf(xj, wu.w, au[k].w);
            av[k].x = fmaf(xj, wv.x, av[k].x); av[k].y = fmaf(xj, wv.y, av[k].y);
            av[k].z = fmaf(xj, wv.z, av[k].z); av[k].w = fmaf(xj, wv.w, av[k].w);
        }
    }
    float4 bb = reinterpret_cast<const float4*>(b2)[q];
#pragma unroll
    for (int k = 0; k < 4; ++k) {
        int i = blockIdx.x * 64 + ty * 4 + k;
        au[k].x += bb.x; au[k].y += bb.y; au[k].z += bb.z; au[k].w += bb.w;
        reinterpret_cast<float4*>(g_A2)[i * 16 + q] = au[k];
        reinterpret_cast<float4*>(g_B2)[i * 16 + q] = av[k];
    }
}

// ---------------------------------------------------------------------------
// K6: h2 = relu(A2 + max_k B2[idx]) -> global max reduce -> (last block)
// out = g @ Wc + bc, then restore invariants (g_gmax=0, g_tick=0).
__global__ __launch_bounds__(256) void k_gmax2(const float* __restrict__ Wc,
                                               const float* __restrict__ bc,
                                               float* __restrict__ out,
                                               int nblocks) {
    __shared__ int sg[HDIM];
    __shared__ bool amLast;
    if (threadIdx.x < HDIM) sg[threadIdx.x] = 0;
    __syncthreads();
    int gt = blockIdx.x * 256 + threadIdx.x;
    int i = gt >> 4, q = gt & 15;
    const int4* row = reinterpret_cast<const int4*>(g_idx + i * KNN);
    float4 m = make_float4(FNINF, FNINF, FNINF, FNINF);
#pragma unroll
    for (int k4 = 0; k4 < 4; ++k4) {
        int4 jj = __ldg(row + k4);
        int js[4] = {jj.x, jj.y, jj.z, jj.w};
#pragma unroll
        for (int e = 0; e < 4; ++e) {
            float4 v = reinterpret_cast<const float4*>(g_B2)[js[e] * 16 + q];
            m.x = fmaxf(m.x, v.x); m.y = fmaxf(m.y, v.y);
            m.z = fmaxf(m.z, v.z); m.w = fmaxf(m.w, v.w);
        }
    }
    float4 a = reinterpret_cast<const float4*>(g_A2)[i * 16 + q];
    float4 o;
    o.x = fmaxf(a.x + m.x, 0.0f); o.y = fmaxf(a.y + m.y, 0.0f);
    o.z = fmaxf(a.z + m.z, 0.0f); o.w = fmaxf(a.w + m.w, 0.0f);
    // relu outputs >= 0, so int-compare == float-compare
    atomicMax(&sg[q * 4 + 0], __float_as_int(o.x));
    atomicMax(&sg[q * 4 + 1], __float_as_int(o.y));
    atomicMax(&sg[q * 4 + 2], __float_as_int(o.z));
    atomicMax(&sg[q * 4 + 3], __float_as_int(o.w));
    __syncthreads();
    if (threadIdx.x < HDIM) atomicMax(&g_gmax[threadIdx.x], sg[threadIdx.x]);

    // ticket: last block computes the output
    __threadfence();
    if (threadIdx.x == 0) {
        int t = atomicAdd(&g_tick, 1);
        amLast = (t == nblocks - 1);
    }
    __syncthreads();
    if (amLast) {
        __shared__ float gv[HDIM];
        int c = threadIdx.x;
        if (c < HDIM) gv[c] = __int_as_float(atomicAdd(&g_gmax[c], 0));
        __syncthreads();
        if (c < CDIM) {
            float acc = bc[c];
#pragma unroll
            for (int h = 0; h < HDIM; ++h)
                acc = fmaf(gv[h], Wc[h * CDIM + c], acc);
            out[c] = acc;
        }
        // restore invariants for next graph replay
        if (c < HDIM) g_gmax[c] = 0;
        if (c == 0) g_tick = 0;
    }
}

// ---------------------------------------------------------------------------
extern "C" void kernel_launch(void* const* d_in, const int* in_sizes, int n_in,
                              void* d_out, int out_size) {
    const float* pos = (const float*)d_in[0];
    // d_in[1] = batch (all zeros, num_segments=1) -> unused
    const float* W1 = (const float*)d_in[2];
    const float* b1 = (const float*)d_in[3];
    const float* W2 = (const float*)d_in[4];
    const float* b2 = (const float*)d_in[5];
    const float* Wc = (const float*)d_in[6];
    const float* bc = (const float*)d_in[7];
    float* out = (float*)d_out;

    k_prep<<<NPTS / 256, 256>>>(pos);                         // 0
    k_scan<<<1, 1024>>>();                                    // 1
    k_scatter<<<NPTS / 256, 256>>>();                         // 2
    k_knng<<<NPTS * 32 / 128, 128>>>(W1, b1);                 // 3  <- ncu slot
    k_feat2<<<NPTS / 64, 256>>>(W2, b2);                      // 4
    k_gmax2<<<NPTS * 16 / 256, 256>>>(Wc, bc, out,
                                      NPTS * 16 / 256);       // 5
}